// round 2
// baseline (speedup 1.0000x reference)
#include <cuda_runtime.h>
#include <cstdint>

#define BB   4
#define NN   8192
#define CIN  128
#define COUT 256
#define MM   2048
#define DMID 64
#define KK   16
#define MAXNN 64
#define G8   8
#define CAP  128
#define R2C  0.01f

// ---------------- scratch (no allocations allowed) ----------------
__device__ int   g_idx[BB][MM];
__device__ float g_xpre[BB][NN][DMID];

// ---------------- FPS: one block per batch ----------------
__global__ __launch_bounds__(256, 1) void fps_kernel(const float* __restrict__ pos) {
    extern __shared__ float sp[];            // [3][NN] SoA, 96KB dynamic
    float* spx = sp;
    float* spy = sp + NN;
    float* spz = sp + 2 * NN;
    __shared__ float swv[8];
    __shared__ int   swi[8];
    __shared__ float bc[3];

    const int b = blockIdx.x, tid = threadIdx.x;
    const float* pb = pos + (size_t)b * NN * 3;

    for (int i = tid; i < NN; i += 256) {
        spx[i] = pb[3 * i + 0];
        spy[i] = pb[3 * i + 1];
        spz[i] = pb[3 * i + 2];
    }
    __syncthreads();

    float lx[32], ly[32], lz[32], md[32];
#pragma unroll
    for (int j = 0; j < 32; j++) {
        int i = j * 256 + tid;
        lx[j] = spx[i]; ly[j] = spy[i]; lz[j] = spz[i];
        md[j] = 3.4e38f;
    }
    if (tid == 0) g_idx[b][0] = 0;

    float cx = spx[0], cy = spy[0], cz = spz[0];

    for (int t = 1; t < MM; t++) {
        float bv = -1.0f;
        int   bi = 0x7fffffff;
#pragma unroll
        for (int j = 0; j < 32; j++) {
            float dx = lx[j] - cx;
            float dy = ly[j] - cy;
            float dz = lz[j] - cz;
            float d2 = fmaf(dz, dz, fmaf(dy, dy, dx * dx));
            float m  = fminf(md[j], d2);
            md[j] = m;
            if (m > bv) { bv = m; bi = j * 256 + tid; }   // ascending idx within thread
        }
        // warp reduce (max value, smaller index on ties)
#pragma unroll
        for (int o = 16; o > 0; o >>= 1) {
            float ov = __shfl_down_sync(0xffffffffu, bv, o);
            int   oi = __shfl_down_sync(0xffffffffu, bi, o);
            if (ov > bv || (ov == bv && oi < bi)) { bv = ov; bi = oi; }
        }
        if ((tid & 31) == 0) { swv[tid >> 5] = bv; swi[tid >> 5] = bi; }
        __syncthreads();
        if (tid == 0) {
            float fv = swv[0]; int fi = swi[0];
#pragma unroll
            for (int w = 1; w < 8; w++) {
                float ov = swv[w]; int oi = swi[w];
                if (ov > fv || (ov == fv && oi < fi)) { fv = ov; fi = oi; }
            }
            g_idx[b][t] = fi;
            bc[0] = spx[fi]; bc[1] = spy[fi]; bc[2] = spz[fi];
        }
        __syncthreads();
        cx = bc[0]; cy = bc[1]; cz = bc[2];
    }
}

// ---------------- x_pre = x @ W_pre + b_pre ----------------
__global__ __launch_bounds__(256) void xpre_kernel(const float* __restrict__ x,
                                                   const float* __restrict__ Wpre,
                                                   const float* __restrict__ bpre) {
    __shared__ float sw[CIN * DMID];     // 32KB
    __shared__ float sx[16][CIN + 4];    // padded vs bank conflicts
    const int tid = threadIdx.x;
    const size_t row0 = (size_t)blockIdx.x * 16;

    for (int i = tid; i < CIN * DMID; i += 256) sw[i] = Wpre[i];
    for (int i = tid; i < 16 * CIN; i += 256) sx[i / CIN][i % CIN] = x[row0 * CIN + i];
    __syncthreads();

    const int r = tid >> 4, cq = tid & 15;
    float4 acc;
    acc.x = bpre[cq * 4 + 0]; acc.y = bpre[cq * 4 + 1];
    acc.z = bpre[cq * 4 + 2]; acc.w = bpre[cq * 4 + 3];
    const float4* sw4 = reinterpret_cast<const float4*>(sw);
#pragma unroll 8
    for (int k = 0; k < CIN; k++) {
        float  a = sx[r][k];
        float4 w = sw4[k * 16 + cq];
        acc.x = fmaf(a, w.x, acc.x); acc.y = fmaf(a, w.y, acc.y);
        acc.z = fmaf(a, w.z, acc.z); acc.w = fmaf(a, w.w, acc.w);
    }
    float4* dst = reinterpret_cast<float4*>(&g_xpre[0][0][0]);
    dst[(row0 + r) * 16 + cq] = acc;
}

// ---------------- conv: 8 centers per block ----------------
struct ConvSmem {
    int   nlist[G8][CAP];
    float nd2[G8][CAP];
    int   cnt[G8];
    int   nsel[G8];
    int   cpt[G8];
    float ccx[G8], ccy[G8], ccz[G8];
    float kpx[KK], kpy[KK], kpz[KK];
    float relx[MAXNN], rely[MAXNN], relz[MAXNN];
    float xjs[MAXNN][DMID];      // 16KB
    float infl[MAXNN][KK];       // 4KB
    float skd[G8][KK][DMID];     // 32KB
    float xc[G8][CIN];           // 4KB
    float F[G8][DMID];           // 2KB
    float fpart[4][G8][DMID];    // 8KB
};

__global__ __launch_bounds__(256, 1) void conv_kernel(
    const float* __restrict__ pos, const float* __restrict__ x,
    const float* __restrict__ kp, const float* __restrict__ kpW,
    const float* __restrict__ Wpost, const float* __restrict__ bpost,
    const float* __restrict__ Wsc, const float* __restrict__ bsc,
    float* __restrict__ out_feat, float* __restrict__ out_pos) {
    extern __shared__ __align__(16) char smraw[];
    ConvSmem& sm = *reinterpret_cast<ConvSmem*>(smraw);
    const int tid = threadIdx.x;
    const int b  = blockIdx.x / (MM / G8);
    const int mg = (blockIdx.x % (MM / G8)) * G8;
    const float* pb = pos + (size_t)b * NN * 3;

    if (tid < G8) {
        int pt = g_idx[b][mg + tid];
        sm.cpt[tid] = pt;
        sm.ccx[tid] = pb[3 * pt + 0];
        sm.ccy[tid] = pb[3 * pt + 1];
        sm.ccz[tid] = pb[3 * pt + 2];
        sm.cnt[tid] = 0;
    }
    if (tid < KK) {
        sm.kpx[tid] = kp[3 * tid + 0];
        sm.kpy[tid] = kp[3 * tid + 1];
        sm.kpz[tid] = kp[3 * tid + 2];
    }
    __syncthreads();

    // shortcut inputs
    for (int i = tid; i < G8 * CIN; i += 256) {
        int g = i >> 7, ci = i & 127;
        sm.xc[g][ci] = x[((size_t)b * NN + sm.cpt[g]) * CIN + ci];
    }

    float gx[G8], gy[G8], gz[G8];
#pragma unroll
    for (int g = 0; g < G8; g++) { gx[g] = sm.ccx[g]; gy[g] = sm.ccy[g]; gz[g] = sm.ccz[g]; }

    // radius scan (exact same d2 expression as FPS / reference)
    for (int i = tid; i < NN; i += 256) {
        float px = pb[3 * i + 0], py = pb[3 * i + 1], pz = pb[3 * i + 2];
#pragma unroll
        for (int g = 0; g < G8; g++) {
            float dx = gx[g] - px, dy = gy[g] - py, dz = gz[g] - pz;
            float d2 = fmaf(dz, dz, fmaf(dy, dy, dx * dx));
            if (d2 <= R2C) {
                int p = atomicAdd(&sm.cnt[g], 1);
                if (p < CAP) { sm.nlist[g][p] = i; sm.nd2[g][p] = d2; }
            }
        }
    }
    __syncthreads();

    // rare overflow: exact 64-nearest selection by (d2, idx) lexicographic
    if (tid < G8) {
        int g = tid;
        int c = sm.cnt[g]; if (c > CAP) c = CAP;
        if (c > MAXNN) {
            for (int s = 0; s < MAXNN; s++) {
                float bvd = 3.4e38f; int bpos = s; int bidx = 0x7fffffff;
                for (int q = s; q < c; q++) {
                    float v = sm.nd2[g][q]; int ii = sm.nlist[g][q];
                    if (v < bvd || (v == bvd && ii < bidx)) { bvd = v; bpos = q; bidx = ii; }
                }
                float tv = sm.nd2[g][s]; int ti = sm.nlist[g][s];
                sm.nd2[g][s] = bvd;  sm.nlist[g][s] = bidx;
                sm.nd2[g][bpos] = tv; sm.nlist[g][bpos] = ti;
            }
            c = MAXNN;
        }
        sm.nsel[g] = c;
    }
    __syncthreads();

    // per-center: influences + s[k][d] accumulation
    for (int g = 0; g < G8; g++) {
        const int ne = sm.nsel[g];
        if (tid < MAXNN && tid < ne) {
            int p = sm.nlist[g][tid];
            sm.relx[tid] = pb[3 * p + 0] - sm.ccx[g];
            sm.rely[tid] = pb[3 * p + 1] - sm.ccy[g];
            sm.relz[tid] = pb[3 * p + 2] - sm.ccz[g];
        }
        for (int i = tid; i < ne * (DMID / 4); i += 256) {
            int e = i >> 4, dq = i & 15;
            const float4* src = reinterpret_cast<const float4*>(&g_xpre[b][sm.nlist[g][e]][0]);
            reinterpret_cast<float4*>(&sm.xjs[e][0])[dq] = src[dq];
        }
        __syncthreads();
        for (int i = tid; i < ne * KK; i += 256) {
            int e = i >> 4, k = i & 15;
            float dx = sm.relx[e] - sm.kpx[k];
            float dy = sm.rely[e] - sm.kpy[k];
            float dz = sm.relz[e] - sm.kpz[k];
            float dd = fmaf(dz, dz, fmaf(dy, dy, dx * dx)) + 1e-12f;
            float dist = sqrtf(dd);
            float v = 1.0f - dist / 0.1f;
            sm.infl[e][k] = v > 0.0f ? v : 0.0f;
        }
        __syncthreads();
        {
            int k = tid >> 4, dq = tid & 15;
            float4 a = make_float4(0.f, 0.f, 0.f, 0.f);
            const float4* xj4 = reinterpret_cast<const float4*>(&sm.xjs[0][0]);
            for (int e = 0; e < ne; e++) {
                float  f  = sm.infl[e][k];
                float4 xv = xj4[e * 16 + dq];
                a.x = fmaf(f, xv.x, a.x); a.y = fmaf(f, xv.y, a.y);
                a.z = fmaf(f, xv.z, a.z); a.w = fmaf(f, xv.w, a.w);
            }
            reinterpret_cast<float4*>(&sm.skd[g][k][0])[dq] = a;
        }
        __syncthreads();
    }

    // F[g][o] = sum_{kd} skd[g][kd] * kpW[kd][o]   (kp_W read once per block)
    {
        int o = tid & 63, p = tid >> 6;       // p in 0..3
        float acc[G8];
#pragma unroll
        for (int g = 0; g < G8; g++) acc[g] = 0.f;
        const float* skdf = &sm.skd[0][0][0];
        for (int kd = p * 256; kd < p * 256 + 256; kd++) {
            float w = kpW[kd * DMID + o];
#pragma unroll
            for (int g = 0; g < G8; g++) acc[g] = fmaf(skdf[g * 1024 + kd], w, acc[g]);
        }
#pragma unroll
        for (int g = 0; g < G8; g++) sm.fpart[p][g][o] = acc[g];
    }
    __syncthreads();
    for (int i = tid; i < G8 * DMID; i += 256) {
        int g = i >> 6, o = i & 63;
        sm.F[g][o] = sm.fpart[0][g][o] + sm.fpart[1][g][o] + sm.fpart[2][g][o] + sm.fpart[3][g][o];
    }
    __syncthreads();

    // out = F @ W_post + b_post + x_center @ W_sc + b_sc
    {
        int c = tid;                 // 0..255
        float acc[G8];
        float bb0 = bpost[c] + bsc[c];
#pragma unroll
        for (int g = 0; g < G8; g++) acc[g] = bb0;
        for (int d = 0; d < DMID; d++) {
            float w = Wpost[d * COUT + c];
#pragma unroll
            for (int g = 0; g < G8; g++) acc[g] = fmaf(sm.F[g][d], w, acc[g]);
        }
        for (int ci = 0; ci < CIN; ci++) {
            float w = Wsc[ci * COUT + c];
#pragma unroll
            for (int g = 0; g < G8; g++) acc[g] = fmaf(sm.xc[g][ci], w, acc[g]);
        }
#pragma unroll
        for (int g = 0; g < G8; g++)
            out_feat[((size_t)b * MM + mg + g) * COUT + c] = acc[g];
    }
    if (tid < G8 * 3) {
        int g = tid / 3, cc = tid % 3;
        float v = (cc == 0) ? sm.ccx[g] : (cc == 1) ? sm.ccy[g] : sm.ccz[g];
        out_pos[((size_t)b * MM + mg + g) * 3 + cc] = v;
    }
}

// ---------------- launch ----------------
extern "C" void kernel_launch(void* const* d_in, const int* in_sizes, int n_in,
                              void* d_out, int out_size) {
    const float* x     = (const float*)d_in[0];
    const float* pos   = (const float*)d_in[1];
    const float* Wpre  = (const float*)d_in[2];
    const float* bpre  = (const float*)d_in[3];
    const float* kp    = (const float*)d_in[4];
    const float* kpW   = (const float*)d_in[5];
    const float* Wpost = (const float*)d_in[6];
    const float* bpost = (const float*)d_in[7];
    const float* Wsc   = (const float*)d_in[8];
    const float* bsc   = (const float*)d_in[9];

    float* out_feat = (float*)d_out;
    float* out_pos  = out_feat + (size_t)BB * MM * COUT;

    cudaFuncSetAttribute(fps_kernel, cudaFuncAttributeMaxDynamicSharedMemorySize, 3 * NN * 4);
    cudaFuncSetAttribute(conv_kernel, cudaFuncAttributeMaxDynamicSharedMemorySize, (int)sizeof(ConvSmem));

    fps_kernel<<<BB, 256, 3 * NN * 4>>>(pos);
    xpre_kernel<<<(BB * NN) / 16, 256>>>(x, Wpre, bpre);
    conv_kernel<<<(BB * MM) / G8, 256, sizeof(ConvSmem)>>>(
        pos, x, kp, kpW, Wpost, bpost, Wsc, bsc, out_feat, out_pos);
}

// round 3
// speedup vs baseline: 1.1973x; 1.1973x over previous
#include <cuda_runtime.h>
#include <cstdint>

#define BB   4
#define NN   8192
#define CIN  128
#define COUT 256
#define MM   2048
#define DMID 64
#define KK   16
#define MAXNN 64
#define G8   8
#define CAP  128
#define R2C  0.01f

#define FPT  512          // fps threads
#define PPT  (NN / FPT)   // 16 points per thread
#define PAIRS (PPT / 2)   // 8

// ---------------- scratch (no allocations allowed) ----------------
__device__ int   g_idx[BB][MM];
__device__ float g_xpre[BB][NN][DMID];

// ---------------- packed f32x2 helpers (bit-identical per lane) ----------------
typedef unsigned long long ull;
__device__ __forceinline__ ull pk2(float a, float b) {
    ull r; asm("mov.b64 %0, {%1, %2};" : "=l"(r) : "f"(a), "f"(b)); return r;
}
__device__ __forceinline__ void upk2(ull v, float& a, float& b) {
    asm("mov.b64 {%0, %1}, %2;" : "=f"(a), "=f"(b) : "l"(v));
}
__device__ __forceinline__ ull add2(ull a, ull b) {
    ull r; asm("add.rn.f32x2 %0, %1, %2;" : "=l"(r) : "l"(a), "l"(b)); return r;
}
__device__ __forceinline__ ull mul2(ull a, ull b) {
    ull r; asm("mul.rn.f32x2 %0, %1, %2;" : "=l"(r) : "l"(a), "l"(b)); return r;
}
__device__ __forceinline__ ull fma2(ull a, ull b, ull c) {
    ull r; asm("fma.rn.f32x2 %0, %1, %2, %3;" : "=l"(r) : "l"(a), "l"(b), "l"(c)); return r;
}

// ---------------- FPS: one block per batch, packed f32x2 main loop ----------------
__global__ __launch_bounds__(FPT, 1) void fps_kernel(const float* __restrict__ pos) {
    extern __shared__ float sp[];            // [3][NN] SoA, 96KB dynamic
    float* spx = sp;
    float* spy = sp + NN;
    float* spz = sp + 2 * NN;
    __shared__ float swv[16];
    __shared__ int   s_sel;
    __shared__ float s_c[3];

    const int b = blockIdx.x, tid = threadIdx.x;
    const int wid = tid >> 5, lane = tid & 31;
    const float* pb = pos + (size_t)b * NN * 3;

    for (int i = tid; i < NN; i += FPT) {
        spx[i] = pb[3 * i + 0];
        spy[i] = pb[3 * i + 1];
        spz[i] = pb[3 * i + 2];
    }
    __syncthreads();

    // register-resident positions, pairs: points (2p)*FPT+tid and (2p+1)*FPT+tid
    ull lx[PAIRS], ly[PAIRS], lz[PAIRS];
    float md[PPT];
#pragma unroll
    for (int p = 0; p < PAIRS; p++) {
        int i0 = (2 * p) * FPT + tid, i1 = i0 + FPT;
        lx[p] = pk2(spx[i0], spx[i1]);
        ly[p] = pk2(spy[i0], spy[i1]);
        lz[p] = pk2(spz[i0], spz[i1]);
    }
#pragma unroll
    for (int j = 0; j < PPT; j++) md[j] = 3.4e38f;

    if (tid == 0) g_idx[b][0] = 0;
    float cx = spx[0], cy = spy[0], cz = spz[0];

    for (int t = 1; t < MM; t++) {
        // negated broadcast center (a + (-c) == a - c exactly)
        ull ncx = pk2(-cx, -cx), ncy = pk2(-cy, -cy), ncz = pk2(-cz, -cz);
        float bvt = -1.0f;
#pragma unroll
        for (int p = 0; p < PAIRS; p++) {
            ull dx = add2(lx[p], ncx);
            ull dy = add2(ly[p], ncy);
            ull dz = add2(lz[p], ncz);
            ull s  = mul2(dx, dx);
            s = fma2(dy, dy, s);
            s = fma2(dz, dz, s);          // same mul->fma->fma order as reference-matching R2
            float t0, t1; upk2(s, t0, t1);
            float m0 = fminf(md[2 * p],     t0); md[2 * p]     = m0;
            float m1 = fminf(md[2 * p + 1], t1); md[2 * p + 1] = m1;
            bvt = fmaxf(bvt, m0);
            bvt = fmaxf(bvt, m1);
        }
        // warp max (value only)
        float bw = bvt;
#pragma unroll
        for (int o = 16; o > 0; o >>= 1) bw = fmaxf(bw, __shfl_xor_sync(0xffffffffu, bw, o));
        if (lane == 0) swv[wid] = bw;
        __syncthreads();
        // block max (every thread folds 16 values; FMNMX chain => exact member of md set)
        const float4* sv4 = reinterpret_cast<const float4*>(swv);
        float4 a0 = sv4[0], a1 = sv4[1], a2 = sv4[2], a3 = sv4[3];
        float bm = fmaxf(fmaxf(fmaxf(a0.x, a0.y), fmaxf(a0.z, a0.w)),
                         fmaxf(fmaxf(a1.x, a1.y), fmaxf(a1.z, a1.w)));
        bm = fmaxf(bm, fmaxf(fmaxf(fmaxf(a2.x, a2.y), fmaxf(a2.z, a2.w)),
                             fmaxf(fmaxf(a3.x, a3.y), fmaxf(a3.z, a3.w))));
        // only the owning thread searches its md[] for the exact max
        if (bvt == bm) {
            int gi = -1;
#pragma unroll
            for (int j = PPT - 1; j >= 0; j--)       // descending => keeps smallest j on ties
                if (md[j] == bm) gi = j * FPT + tid;
            if (gi >= 0) {
                s_sel = gi;
                g_idx[b][t] = gi;
                s_c[0] = spx[gi]; s_c[1] = spy[gi]; s_c[2] = spz[gi];
            }
        }
        __syncthreads();
        cx = s_c[0]; cy = s_c[1]; cz = s_c[2];
    }
}

// ---------------- x_pre = x @ W_pre + b_pre ----------------
__global__ __launch_bounds__(256) void xpre_kernel(const float* __restrict__ x,
                                                   const float* __restrict__ Wpre,
                                                   const float* __restrict__ bpre) {
    __shared__ float sw[CIN * DMID];     // 32KB
    __shared__ float sx[16][CIN + 4];    // padded vs bank conflicts
    const int tid = threadIdx.x;
    const size_t row0 = (size_t)blockIdx.x * 16;

    for (int i = tid; i < CIN * DMID; i += 256) sw[i] = Wpre[i];
    for (int i = tid; i < 16 * CIN; i += 256) sx[i / CIN][i % CIN] = x[row0 * CIN + i];
    __syncthreads();

    const int r = tid >> 4, cq = tid & 15;
    float4 acc;
    acc.x = bpre[cq * 4 + 0]; acc.y = bpre[cq * 4 + 1];
    acc.z = bpre[cq * 4 + 2]; acc.w = bpre[cq * 4 + 3];
    const float4* sw4 = reinterpret_cast<const float4*>(sw);
#pragma unroll 8
    for (int k = 0; k < CIN; k++) {
        float  a = sx[r][k];
        float4 w = sw4[k * 16 + cq];
        acc.x = fmaf(a, w.x, acc.x); acc.y = fmaf(a, w.y, acc.y);
        acc.z = fmaf(a, w.z, acc.z); acc.w = fmaf(a, w.w, acc.w);
    }
    float4* dst = reinterpret_cast<float4*>(&g_xpre[0][0][0]);
    dst[(row0 + r) * 16 + cq] = acc;
}

// ---------------- conv: 8 centers per block ----------------
struct ConvSmem {
    int   nlist[G8][CAP];
    float nd2[G8][CAP];
    int   cnt[G8];
    int   nsel[G8];
    int   cpt[G8];
    float ccx[G8], ccy[G8], ccz[G8];
    float kpx[KK], kpy[KK], kpz[KK];
    float relx[MAXNN], rely[MAXNN], relz[MAXNN];
    float xjs[MAXNN][DMID];      // 16KB
    float infl[MAXNN][KK];       // 4KB
    float skd[G8][KK][DMID];     // 32KB
    float xc[G8][CIN];           // 4KB
    float F[G8][DMID];           // 2KB
    float fpart[4][G8][DMID];    // 8KB
};

__global__ __launch_bounds__(256, 1) void conv_kernel(
    const float* __restrict__ pos, const float* __restrict__ x,
    const float* __restrict__ kp, const float* __restrict__ kpW,
    const float* __restrict__ Wpost, const float* __restrict__ bpost,
    const float* __restrict__ Wsc, const float* __restrict__ bsc,
    float* __restrict__ out_feat, float* __restrict__ out_pos) {
    extern __shared__ __align__(16) char smraw[];
    ConvSmem& sm = *reinterpret_cast<ConvSmem*>(smraw);
    const int tid = threadIdx.x;
    const int b  = blockIdx.x / (MM / G8);
    const int mg = (blockIdx.x % (MM / G8)) * G8;
    const float* pb = pos + (size_t)b * NN * 3;

    if (tid < G8) {
        int pt = g_idx[b][mg + tid];
        sm.cpt[tid] = pt;
        sm.ccx[tid] = pb[3 * pt + 0];
        sm.ccy[tid] = pb[3 * pt + 1];
        sm.ccz[tid] = pb[3 * pt + 2];
        sm.cnt[tid] = 0;
    }
    if (tid < KK) {
        sm.kpx[tid] = kp[3 * tid + 0];
        sm.kpy[tid] = kp[3 * tid + 1];
        sm.kpz[tid] = kp[3 * tid + 2];
    }
    __syncthreads();

    // shortcut inputs
    for (int i = tid; i < G8 * CIN; i += 256) {
        int g = i >> 7, ci = i & 127;
        sm.xc[g][ci] = x[((size_t)b * NN + sm.cpt[g]) * CIN + ci];
    }

    float gx[G8], gy[G8], gz[G8];
#pragma unroll
    for (int g = 0; g < G8; g++) { gx[g] = sm.ccx[g]; gy[g] = sm.ccy[g]; gz[g] = sm.ccz[g]; }

    // radius scan (exact same d2 expression as FPS / reference)
    for (int i = tid; i < NN; i += 256) {
        float px = pb[3 * i + 0], py = pb[3 * i + 1], pz = pb[3 * i + 2];
#pragma unroll
        for (int g = 0; g < G8; g++) {
            float dx = gx[g] - px, dy = gy[g] - py, dz = gz[g] - pz;
            float d2 = fmaf(dz, dz, fmaf(dy, dy, dx * dx));
            if (d2 <= R2C) {
                int p = atomicAdd(&sm.cnt[g], 1);
                if (p < CAP) { sm.nlist[g][p] = i; sm.nd2[g][p] = d2; }
            }
        }
    }
    __syncthreads();

    // rare overflow: exact 64-nearest selection by (d2, idx) lexicographic
    if (tid < G8) {
        int g = tid;
        int c = sm.cnt[g]; if (c > CAP) c = CAP;
        if (c > MAXNN) {
            for (int s = 0; s < MAXNN; s++) {
                float bvd = 3.4e38f; int bpos = s; int bidx = 0x7fffffff;
                for (int q = s; q < c; q++) {
                    float v = sm.nd2[g][q]; int ii = sm.nlist[g][q];
                    if (v < bvd || (v == bvd && ii < bidx)) { bvd = v; bpos = q; bidx = ii; }
                }
                float tv = sm.nd2[g][s]; int ti = sm.nlist[g][s];
                sm.nd2[g][s] = bvd;  sm.nlist[g][s] = bidx;
                sm.nd2[g][bpos] = tv; sm.nlist[g][bpos] = ti;
            }
            c = MAXNN;
        }
        sm.nsel[g] = c;
    }
    __syncthreads();

    // per-center: influences + s[k][d] accumulation
    for (int g = 0; g < G8; g++) {
        const int ne = sm.nsel[g];
        if (tid < MAXNN && tid < ne) {
            int p = sm.nlist[g][tid];
            sm.relx[tid] = pb[3 * p + 0] - sm.ccx[g];
            sm.rely[tid] = pb[3 * p + 1] - sm.ccy[g];
            sm.relz[tid] = pb[3 * p + 2] - sm.ccz[g];
        }
        for (int i = tid; i < ne * (DMID / 4); i += 256) {
            int e = i >> 4, dq = i & 15;
            const float4* src = reinterpret_cast<const float4*>(&g_xpre[b][sm.nlist[g][e]][0]);
            reinterpret_cast<float4*>(&sm.xjs[e][0])[dq] = src[dq];
        }
        __syncthreads();
        for (int i = tid; i < ne * KK; i += 256) {
            int e = i >> 4, k = i & 15;
            float dx = sm.relx[e] - sm.kpx[k];
            float dy = sm.rely[e] - sm.kpy[k];
            float dz = sm.relz[e] - sm.kpz[k];
            float dd = fmaf(dz, dz, fmaf(dy, dy, dx * dx)) + 1e-12f;
            float dist = sqrtf(dd);
            float v = 1.0f - dist / 0.1f;
            sm.infl[e][k] = v > 0.0f ? v : 0.0f;
        }
        __syncthreads();
        {
            int k = tid >> 4, dq = tid & 15;
            float4 a = make_float4(0.f, 0.f, 0.f, 0.f);
            const float4* xj4 = reinterpret_cast<const float4*>(&sm.xjs[0][0]);
            for (int e = 0; e < ne; e++) {
                float  f  = sm.infl[e][k];
                float4 xv = xj4[e * 16 + dq];
                a.x = fmaf(f, xv.x, a.x); a.y = fmaf(f, xv.y, a.y);
                a.z = fmaf(f, xv.z, a.z); a.w = fmaf(f, xv.w, a.w);
            }
            reinterpret_cast<float4*>(&sm.skd[g][k][0])[dq] = a;
        }
        __syncthreads();
    }

    // F[g][o] = sum_{kd} skd[g][kd] * kpW[kd][o]   (kp_W read once per block)
    {
        int o = tid & 63, p = tid >> 6;       // p in 0..3
        float acc[G8];
#pragma unroll
        for (int g = 0; g < G8; g++) acc[g] = 0.f;
        const float* skdf = &sm.skd[0][0][0];
        for (int kd = p * 256; kd < p * 256 + 256; kd++) {
            float w = kpW[kd * DMID + o];
#pragma unroll
            for (int g = 0; g < G8; g++) acc[g] = fmaf(skdf[g * 1024 + kd], w, acc[g]);
        }
#pragma unroll
        for (int g = 0; g < G8; g++) sm.fpart[p][g][o] = acc[g];
    }
    __syncthreads();
    for (int i = tid; i < G8 * DMID; i += 256) {
        int g = i >> 6, o = i & 63;
        sm.F[g][o] = sm.fpart[0][g][o] + sm.fpart[1][g][o] + sm.fpart[2][g][o] + sm.fpart[3][g][o];
    }
    __syncthreads();

    // out = F @ W_post + b_post + x_center @ W_sc + b_sc
    {
        int c = tid;                 // 0..255
        float acc[G8];
        float bb0 = bpost[c] + bsc[c];
#pragma unroll
        for (int g = 0; g < G8; g++) acc[g] = bb0;
        for (int d = 0; d < DMID; d++) {
            float w = Wpost[d * COUT + c];
#pragma unroll
            for (int g = 0; g < G8; g++) acc[g] = fmaf(sm.F[g][d], w, acc[g]);
        }
        for (int ci = 0; ci < CIN; ci++) {
            float w = Wsc[ci * COUT + c];
#pragma unroll
            for (int g = 0; g < G8; g++) acc[g] = fmaf(sm.xc[g][ci], w, acc[g]);
        }
#pragma unroll
        for (int g = 0; g < G8; g++)
            out_feat[((size_t)b * MM + mg + g) * COUT + c] = acc[g];
    }
    if (tid < G8 * 3) {
        int g = tid / 3, cc = tid % 3;
        float v = (cc == 0) ? sm.ccx[g] : (cc == 1) ? sm.ccy[g] : sm.ccz[g];
        out_pos[((size_t)b * MM + mg + g) * 3 + cc] = v;
    }
}

// ---------------- launch ----------------
extern "C" void kernel_launch(void* const* d_in, const int* in_sizes, int n_in,
                              void* d_out, int out_size) {
    const float* x     = (const float*)d_in[0];
    const float* pos   = (const float*)d_in[1];
    const float* Wpre  = (const float*)d_in[2];
    const float* bpre  = (const float*)d_in[3];
    const float* kp    = (const float*)d_in[4];
    const float* kpW   = (const float*)d_in[5];
    const float* Wpost = (const float*)d_in[6];
    const float* bpost = (const float*)d_in[7];
    const float* Wsc   = (const float*)d_in[8];
    const float* bsc   = (const float*)d_in[9];

    float* out_feat = (float*)d_out;
    float* out_pos  = out_feat + (size_t)BB * MM * COUT;

    cudaFuncSetAttribute(fps_kernel, cudaFuncAttributeMaxDynamicSharedMemorySize, 3 * NN * 4);
    cudaFuncSetAttribute(conv_kernel, cudaFuncAttributeMaxDynamicSharedMemorySize, (int)sizeof(ConvSmem));

    fps_kernel<<<BB, FPT, 3 * NN * 4>>>(pos);
    xpre_kernel<<<(BB * NN) / 16, 256>>>(x, Wpre, bpre);
    conv_kernel<<<(BB * MM) / G8, 256, sizeof(ConvSmem)>>>(
        pos, x, kp, kpW, Wpost, bpost, Wsc, bsc, out_feat, out_pos);
}

// round 4
// speedup vs baseline: 1.3768x; 1.1499x over previous
#include <cuda_runtime.h>
#include <cstdint>

#define BB   4
#define NN   8192
#define CIN  128
#define COUT 256
#define MM   2048
#define DMID 64
#define KK   16
#define MAXNN 64
#define G8   8
#define CAP  128
#define R2C  0.01f

#define FPT  512          // fps threads
#define PPT  (NN / FPT)   // 16 points per thread
#define PAIRS (PPT / 2)   // 8
#define XROWS 32          // xpre rows per block (512 threads)

// ---------------- scratch (no allocations allowed) ----------------
__device__ int   g_idx[BB][MM];
__device__ float g_xpre[BB][NN][DMID];

// ---------------- packed f32x2 helpers (bit-identical per lane) ----------------
typedef unsigned long long ull;
__device__ __forceinline__ ull pk2(float a, float b) {
    ull r; asm("mov.b64 %0, {%1, %2};" : "=l"(r) : "f"(a), "f"(b)); return r;
}
__device__ __forceinline__ void upk2(ull v, float& a, float& b) {
    asm("mov.b64 {%0, %1}, %2;" : "=f"(a), "=f"(b) : "l"(v));
}
__device__ __forceinline__ ull add2(ull a, ull b) {
    ull r; asm("add.rn.f32x2 %0, %1, %2;" : "=l"(r) : "l"(a), "l"(b)); return r;
}
__device__ __forceinline__ ull mul2(ull a, ull b) {
    ull r; asm("mul.rn.f32x2 %0, %1, %2;" : "=l"(r) : "l"(a), "l"(b)); return r;
}
__device__ __forceinline__ ull fma2(ull a, ull b, ull c) {
    ull r; asm("fma.rn.f32x2 %0, %1, %2, %3;" : "=l"(r) : "l"(a), "l"(b), "l"(c)); return r;
}
__device__ __forceinline__ unsigned redux_max_u32(unsigned v) {
    unsigned r; asm("redux.sync.max.u32 %0, %1, 0xffffffff;" : "=r"(r) : "r"(v)); return r;
}

// ---------------- fused: FPS (blocks 0..3) + x_pre GEMM (blocks 4..) ----------------
__global__ __launch_bounds__(FPT, 1) void fps_xpre_kernel(
    const float* __restrict__ pos, const float* __restrict__ x,
    const float* __restrict__ Wpre, const float* __restrict__ bpre) {
    extern __shared__ float sp[];            // 96KB dynamic
    const int tid = threadIdx.x;

    if (blockIdx.x < BB) {
        // ================= FPS: one block per batch =================
        float* spx = sp;
        float* spy = sp + NN;
        float* spz = sp + 2 * NN;
        __shared__ unsigned swv[16];
        __shared__ float s_c[3];

        const int b = blockIdx.x;
        const int wid = tid >> 5, lane = tid & 31;
        const float* pb = pos + (size_t)b * NN * 3;

        for (int i = tid; i < NN; i += FPT) {
            spx[i] = pb[3 * i + 0];
            spy[i] = pb[3 * i + 1];
            spz[i] = pb[3 * i + 2];
        }
        __syncthreads();

        ull lx[PAIRS], ly[PAIRS], lz[PAIRS];
        float md[PPT];
#pragma unroll
        for (int p = 0; p < PAIRS; p++) {
            int i0 = (2 * p) * FPT + tid, i1 = i0 + FPT;
            lx[p] = pk2(spx[i0], spx[i1]);
            ly[p] = pk2(spy[i0], spy[i1]);
            lz[p] = pk2(spz[i0], spz[i1]);
        }
#pragma unroll
        for (int j = 0; j < PPT; j++) md[j] = 3.4e38f;

        if (tid == 0) g_idx[b][0] = 0;
        float cx = spx[0], cy = spy[0], cz = spz[0];

        for (int t = 1; t < MM; t++) {
            ull ncx = pk2(-cx, -cx), ncy = pk2(-cy, -cy), ncz = pk2(-cz, -cz);
            float bvt = 0.0f;
#pragma unroll
            for (int p = 0; p < PAIRS; p++) {
                ull dx = add2(lx[p], ncx);                 // exact (p - c)
                ull dy = add2(ly[p], ncy);
                ull dz = add2(lz[p], ncz);
                ull s  = mul2(dx, dx);
                s = fma2(dy, dy, s);
                s = fma2(dz, dz, s);                       // same contraction as reference-matched
                float t0, t1; upk2(s, t0, t1);
                float m0 = fminf(md[2 * p],     t0); md[2 * p]     = m0;
                float m1 = fminf(md[2 * p + 1], t1); md[2 * p + 1] = m1;
                bvt = fmaxf(bvt, m0);
                bvt = fmaxf(bvt, m1);
            }
            // warp max via HW redux on float bits (all values >= 0 => bit-monotone)
            unsigned bvb = __float_as_uint(bvt);
            unsigned bw = redux_max_u32(bvb);
            if (lane == 0) swv[wid] = bw;
            __syncthreads();
            // block max: fold 16 bit-values
            const uint4* sv4 = reinterpret_cast<const uint4*>(swv);
            uint4 a0 = sv4[0], a1 = sv4[1], a2 = sv4[2], a3 = sv4[3];
            unsigned bm = max(max(max(a0.x, a0.y), max(a0.z, a0.w)),
                              max(max(a1.x, a1.y), max(a1.z, a1.w)));
            bm = max(bm, max(max(max(a2.x, a2.y), max(a2.z, a2.w)),
                             max(max(a3.x, a3.y), max(a3.z, a3.w))));
            // only the owning thread searches its md[] for the exact max
            if (bvb == bm) {
                int gi = -1;
#pragma unroll
                for (int j = PPT - 1; j >= 0; j--)          // descending => smallest j on ties
                    if (__float_as_uint(md[j]) == bm) gi = j * FPT + tid;
                if (gi >= 0) {
                    g_idx[b][t] = gi;
                    s_c[0] = spx[gi]; s_c[1] = spy[gi]; s_c[2] = spz[gi];
                }
            }
            __syncthreads();
            cx = s_c[0]; cy = s_c[1]; cz = s_c[2];
        }
    } else {
        // ================= x_pre = x @ W_pre + b_pre =================
        float* sw = sp;                         // CIN*DMID = 8192 floats
        float* sx = sp + CIN * DMID;            // XROWS * (CIN+4)
        const int bx = blockIdx.x - BB;
        const size_t row0 = (size_t)bx * XROWS;

        for (int i = tid; i < CIN * DMID; i += FPT) sw[i] = Wpre[i];
        for (int i = tid; i < XROWS * CIN; i += FPT)
            sx[(i >> 7) * (CIN + 4) + (i & 127)] = x[row0 * CIN + i];
        __syncthreads();

        const int r = tid >> 4, cq = tid & 15;
        float4 acc;
        acc.x = bpre[cq * 4 + 0]; acc.y = bpre[cq * 4 + 1];
        acc.z = bpre[cq * 4 + 2]; acc.w = bpre[cq * 4 + 3];
        const float4* sw4 = reinterpret_cast<const float4*>(sw);
#pragma unroll 8
        for (int k = 0; k < CIN; k++) {
            float  a = sx[r * (CIN + 4) + k];
            float4 w = sw4[k * 16 + cq];
            acc.x = fmaf(a, w.x, acc.x); acc.y = fmaf(a, w.y, acc.y);
            acc.z = fmaf(a, w.z, acc.z); acc.w = fmaf(a, w.w, acc.w);
        }
        float4* dst = reinterpret_cast<float4*>(&g_xpre[0][0][0]);
        dst[(row0 + r) * 16 + cq] = acc;
    }
}

// ---------------- conv: 8 centers per block ----------------
struct ConvSmem {
    int   nlist[G8][CAP];
    float nd2[G8][CAP];
    int   cnt[G8];
    int   nsel[G8];
    int   cpt[G8];
    float ccx[G8], ccy[G8], ccz[G8];
    float kpx[KK], kpy[KK], kpz[KK];
    float relx[MAXNN], rely[MAXNN], relz[MAXNN];
    float xjs[MAXNN][DMID];      // 16KB
    float infl[MAXNN][KK];       // 4KB
    float skd[G8][KK][DMID];     // 32KB
    float xc[G8][CIN];           // 4KB
    float F[G8][DMID];           // 2KB
    float fpart[4][G8][DMID];    // 8KB
};

__global__ __launch_bounds__(256, 1) void conv_kernel(
    const float* __restrict__ pos, const float* __restrict__ x,
    const float* __restrict__ kp, const float* __restrict__ kpW,
    const float* __restrict__ Wpost, const float* __restrict__ bpost,
    const float* __restrict__ Wsc, const float* __restrict__ bsc,
    float* __restrict__ out_feat, float* __restrict__ out_pos) {
    extern __shared__ __align__(16) char smraw[];
    ConvSmem& sm = *reinterpret_cast<ConvSmem*>(smraw);
    const int tid = threadIdx.x;
    const int b  = blockIdx.x / (MM / G8);
    const int mg = (blockIdx.x % (MM / G8)) * G8;
    const float* pb = pos + (size_t)b * NN * 3;

    if (tid < G8) {
        int pt = g_idx[b][mg + tid];
        sm.cpt[tid] = pt;
        sm.ccx[tid] = pb[3 * pt + 0];
        sm.ccy[tid] = pb[3 * pt + 1];
        sm.ccz[tid] = pb[3 * pt + 2];
        sm.cnt[tid] = 0;
    }
    if (tid < KK) {
        sm.kpx[tid] = kp[3 * tid + 0];
        sm.kpy[tid] = kp[3 * tid + 1];
        sm.kpz[tid] = kp[3 * tid + 2];
    }
    __syncthreads();

    // shortcut inputs
    for (int i = tid; i < G8 * CIN; i += 256) {
        int g = i >> 7, ci = i & 127;
        sm.xc[g][ci] = x[((size_t)b * NN + sm.cpt[g]) * CIN + ci];
    }

    // packed center pairs
    ull cx2[G8 / 2], cy2[G8 / 2], cz2[G8 / 2];
#pragma unroll
    for (int gp = 0; gp < G8 / 2; gp++) {
        cx2[gp] = pk2(sm.ccx[2 * gp], sm.ccx[2 * gp + 1]);
        cy2[gp] = pk2(sm.ccy[2 * gp], sm.ccy[2 * gp + 1]);
        cz2[gp] = pk2(sm.ccz[2 * gp], sm.ccz[2 * gp + 1]);
    }

    // radius scan, packed: d2 = (c-p)^2 with exact sub via add of negation
    for (int i = tid; i < NN; i += 256) {
        float px = pb[3 * i + 0], py = pb[3 * i + 1], pz = pb[3 * i + 2];
        ull npx = pk2(-px, -px), npy = pk2(-py, -py), npz = pk2(-pz, -pz);
#pragma unroll
        for (int gp = 0; gp < G8 / 2; gp++) {
            ull dx = add2(cx2[gp], npx);
            ull dy = add2(cy2[gp], npy);
            ull dz = add2(cz2[gp], npz);
            ull s  = mul2(dx, dx);
            s = fma2(dy, dy, s);
            s = fma2(dz, dz, s);
            float d0, d1; upk2(s, d0, d1);
            if (d0 <= R2C) {
                int p = atomicAdd(&sm.cnt[2 * gp], 1);
                if (p < CAP) { sm.nlist[2 * gp][p] = i; sm.nd2[2 * gp][p] = d0; }
            }
            if (d1 <= R2C) {
                int p = atomicAdd(&sm.cnt[2 * gp + 1], 1);
                if (p < CAP) { sm.nlist[2 * gp + 1][p] = i; sm.nd2[2 * gp + 1][p] = d1; }
            }
        }
    }
    __syncthreads();

    // rare overflow: exact 64-nearest selection by (d2, idx) lexicographic
    if (tid < G8) {
        int g = tid;
        int c = sm.cnt[g]; if (c > CAP) c = CAP;
        if (c > MAXNN) {
            for (int s = 0; s < MAXNN; s++) {
                float bvd = 3.4e38f; int bpos = s; int bidx = 0x7fffffff;
                for (int q = s; q < c; q++) {
                    float v = sm.nd2[g][q]; int ii = sm.nlist[g][q];
                    if (v < bvd || (v == bvd && ii < bidx)) { bvd = v; bpos = q; bidx = ii; }
                }
                float tv = sm.nd2[g][s]; int ti = sm.nlist[g][s];
                sm.nd2[g][s] = bvd;  sm.nlist[g][s] = bidx;
                sm.nd2[g][bpos] = tv; sm.nlist[g][bpos] = ti;
            }
            c = MAXNN;
        }
        sm.nsel[g] = c;
    }
    __syncthreads();

    // per-center: influences + s[k][d] accumulation
    for (int g = 0; g < G8; g++) {
        const int ne = sm.nsel[g];
        if (tid < MAXNN && tid < ne) {
            int p = sm.nlist[g][tid];
            sm.relx[tid] = pb[3 * p + 0] - sm.ccx[g];
            sm.rely[tid] = pb[3 * p + 1] - sm.ccy[g];
            sm.relz[tid] = pb[3 * p + 2] - sm.ccz[g];
        }
        for (int i = tid; i < ne * (DMID / 4); i += 256) {
            int e = i >> 4, dq = i & 15;
            const float4* src = reinterpret_cast<const float4*>(&g_xpre[b][sm.nlist[g][e]][0]);
            reinterpret_cast<float4*>(&sm.xjs[e][0])[dq] = src[dq];
        }
        __syncthreads();
        for (int i = tid; i < ne * KK; i += 256) {
            int e = i >> 4, k = i & 15;
            float dx = sm.relx[e] - sm.kpx[k];
            float dy = sm.rely[e] - sm.kpy[k];
            float dz = sm.relz[e] - sm.kpz[k];
            float dd = fmaf(dz, dz, fmaf(dy, dy, dx * dx)) + 1e-12f;
            float dist = sqrtf(dd);
            float v = 1.0f - dist / 0.1f;
            sm.infl[e][k] = v > 0.0f ? v : 0.0f;
        }
        __syncthreads();
        {
            int k = tid >> 4, dq = tid & 15;
            float4 a = make_float4(0.f, 0.f, 0.f, 0.f);
            const float4* xj4 = reinterpret_cast<const float4*>(&sm.xjs[0][0]);
            for (int e = 0; e < ne; e++) {
                float  f  = sm.infl[e][k];
                float4 xv = xj4[e * 16 + dq];
                a.x = fmaf(f, xv.x, a.x); a.y = fmaf(f, xv.y, a.y);
                a.z = fmaf(f, xv.z, a.z); a.w = fmaf(f, xv.w, a.w);
            }
            reinterpret_cast<float4*>(&sm.skd[g][k][0])[dq] = a;
        }
        __syncthreads();
    }

    // F[g][o] = sum_{kd} skd[g][kd] * kpW[kd][o]
    {
        int o = tid & 63, p = tid >> 6;       // p in 0..3
        float acc[G8];
#pragma unroll
        for (int g = 0; g < G8; g++) acc[g] = 0.f;
        const float* skdf = &sm.skd[0][0][0];
        for (int kd = p * 256; kd < p * 256 + 256; kd++) {
            float w = kpW[kd * DMID + o];
#pragma unroll
            for (int g = 0; g < G8; g++) acc[g] = fmaf(skdf[g * 1024 + kd], w, acc[g]);
        }
#pragma unroll
        for (int g = 0; g < G8; g++) sm.fpart[p][g][o] = acc[g];
    }
    __syncthreads();
    for (int i = tid; i < G8 * DMID; i += 256) {
        int g = i >> 6, o = i & 63;
        sm.F[g][o] = sm.fpart[0][g][o] + sm.fpart[1][g][o] + sm.fpart[2][g][o] + sm.fpart[3][g][o];
    }
    __syncthreads();

    // out = F @ W_post + b_post + x_center @ W_sc + b_sc
    {
        int c = tid;                 // 0..255
        float acc[G8];
        float bb0 = bpost[c] + bsc[c];
#pragma unroll
        for (int g = 0; g < G8; g++) acc[g] = bb0;
        for (int d = 0; d < DMID; d++) {
            float w = Wpost[d * COUT + c];
#pragma unroll
            for (int g = 0; g < G8; g++) acc[g] = fmaf(sm.F[g][d], w, acc[g]);
        }
        for (int ci = 0; ci < CIN; ci++) {
            float w = Wsc[ci * COUT + c];
#pragma unroll
            for (int g = 0; g < G8; g++) acc[g] = fmaf(sm.xc[g][ci], w, acc[g]);
        }
#pragma unroll
        for (int g = 0; g < G8; g++)
            out_feat[((size_t)b * MM + mg + g) * COUT + c] = acc[g];
    }
    if (tid < G8 * 3) {
        int g = tid / 3, cc = tid % 3;
        float v = (cc == 0) ? sm.ccx[g] : (cc == 1) ? sm.ccy[g] : sm.ccz[g];
        out_pos[((size_t)b * MM + mg + g) * 3 + cc] = v;
    }
}

// ---------------- launch ----------------
extern "C" void kernel_launch(void* const* d_in, const int* in_sizes, int n_in,
                              void* d_out, int out_size) {
    const float* x     = (const float*)d_in[0];
    const float* pos   = (const float*)d_in[1];
    const float* Wpre  = (const float*)d_in[2];
    const float* bpre  = (const float*)d_in[3];
    const float* kp    = (const float*)d_in[4];
    const float* kpW   = (const float*)d_in[5];
    const float* Wpost = (const float*)d_in[6];
    const float* bpost = (const float*)d_in[7];
    const float* Wsc   = (const float*)d_in[8];
    const float* bsc   = (const float*)d_in[9];

    float* out_feat = (float*)d_out;
    float* out_pos  = out_feat + (size_t)BB * MM * COUT;

    cudaFuncSetAttribute(fps_xpre_kernel, cudaFuncAttributeMaxDynamicSharedMemorySize, 3 * NN * 4);
    cudaFuncSetAttribute(conv_kernel, cudaFuncAttributeMaxDynamicSharedMemorySize, (int)sizeof(ConvSmem));

    int xblocks = (BB * NN) / XROWS;   // 1024
    fps_xpre_kernel<<<BB + xblocks, FPT, 3 * NN * 4>>>(pos, x, Wpre, bpre);
    conv_kernel<<<(BB * MM) / G8, 256, sizeof(ConvSmem)>>>(
        pos, x, kp, kpW, Wpost, bpost, Wsc, bsc, out_feat, out_pos);
}

// round 7
// speedup vs baseline: 1.5604x; 1.1334x over previous
#include <cuda_runtime.h>
#include <cstdint>

#define BB   4
#define NN   8192
#define CIN  128
#define COUT 256
#define MM   2048
#define DMID 64
#define KK   16
#define MAXNN 64
#define G8   8
#define CAP  128
#define R2C  0.01f

#define FPT  1024                 // fps threads
#define PPT  (NN / FPT)           // 8 points per thread
#define PAIRS (PPT / 2)           // 4
#define XPT  512                  // xpre active threads
#define XROWS 32
#define XBLOCKS ((BB * NN) / XROWS)   // 1024
#define CONVBLOCKS ((BB * MM) / G8)   // 1024

// ---------------- scratch (no allocations allowed) ----------------
__device__ int   g_idx[BB][MM];
__device__ float g_xpre[BB][NN][DMID];
__device__ int   g_prog[BB];
__device__ int   g_xdone;

// ---------------- packed f32x2 helpers (bit-identical per lane) ----------------
typedef unsigned long long ull;
__device__ __forceinline__ ull pk2(float a, float b) {
    ull r; asm("mov.b64 %0, {%1, %2};" : "=l"(r) : "f"(a), "f"(b)); return r;
}
__device__ __forceinline__ void upk2(ull v, float& a, float& b) {
    asm("mov.b64 {%0, %1}, %2;" : "=f"(a), "=f"(b) : "l"(v));
}
__device__ __forceinline__ ull add2(ull a, ull b) {
    ull r; asm("add.rn.f32x2 %0, %1, %2;" : "=l"(r) : "l"(a), "l"(b)); return r;
}
__device__ __forceinline__ ull mul2(ull a, ull b) {
    ull r; asm("mul.rn.f32x2 %0, %1, %2;" : "=l"(r) : "l"(a), "l"(b)); return r;
}
__device__ __forceinline__ ull fma2(ull a, ull b, ull c) {
    ull r; asm("fma.rn.f32x2 %0, %1, %2, %3;" : "=l"(r) : "l"(a), "l"(b), "l"(c)); return r;
}
__device__ __forceinline__ unsigned redux_max_u32(unsigned v) {
    unsigned r; asm("redux.sync.max.u32 %0, %1, 0xffffffff;" : "=r"(r) : "r"(v)); return r;
}

// ---------------- init: reset progress flags (fresh every graph replay) ----------------
__global__ void init_kernel() {
    int t = threadIdx.x;
    if (t < BB) g_prog[t] = 0;
    if (t == 0) g_xdone = 0;
}

// ---------------- conv shared layout ----------------
struct ConvSmem {
    int   nlist[G8][CAP];
    float nd2[G8][CAP];
    int   cnt[G8];
    int   nsel[G8];
    int   cpt[G8];
    float ccx[G8], ccy[G8], ccz[G8];
    float kpx[KK], kpy[KK], kpz[KK];
    float relx[MAXNN], rely[MAXNN], relz[MAXNN];
    float xjs[MAXNN][DMID];      // 16KB
    float infl[MAXNN][KK];       // 4KB
    float skd[G8][KK][DMID];     // 32KB
    float xc[G8][CIN];           // 4KB
    float F[G8][DMID];           // 2KB
    float fpart[4][G8][DMID];    // 8KB
};

// ================================================================
// mega kernel: blocks 0..3 FPS | 4..4+XBLOCKS-1 xpre | rest conv
// ================================================================
__global__ __launch_bounds__(FPT, 1) void mega_kernel(
    const float* __restrict__ pos, const float* __restrict__ x,
    const float* __restrict__ Wpre, const float* __restrict__ bpre,
    const float* __restrict__ kp, const float* __restrict__ kpW,
    const float* __restrict__ Wpost, const float* __restrict__ bpost,
    const float* __restrict__ Wsc, const float* __restrict__ bsc,
    float* __restrict__ out_feat, float* __restrict__ out_pos) {
    extern __shared__ __align__(16) float sp[];     // 96KB dynamic
    const int tid = threadIdx.x;

    if (blockIdx.x < BB) {
        // ===================== FPS: one block per batch, 1024 threads =====================
        float* spx = sp;
        float* spy = sp + NN;
        float* spz = sp + 2 * NN;
        __shared__ unsigned swv[32];
        __shared__ float s_c[3];

        const int b = blockIdx.x;
        const int wid = tid >> 5, lane = tid & 31;
        const float* pb = pos + (size_t)b * NN * 3;

        for (int i = tid; i < NN; i += FPT) {
            spx[i] = pb[3 * i + 0];
            spy[i] = pb[3 * i + 1];
            spz[i] = pb[3 * i + 2];
        }
        __syncthreads();

        ull lx[PAIRS], ly[PAIRS], lz[PAIRS];
        float md[PPT];
#pragma unroll
        for (int p = 0; p < PAIRS; p++) {
            int i0 = (2 * p) * FPT + tid, i1 = i0 + FPT;
            lx[p] = pk2(spx[i0], spx[i1]);
            ly[p] = pk2(spy[i0], spy[i1]);
            lz[p] = pk2(spz[i0], spz[i1]);
        }
#pragma unroll
        for (int j = 0; j < PPT; j++) md[j] = 3.4e38f;

        if (tid == 0) g_idx[b][0] = 0;
        float cx = spx[0], cy = spy[0], cz = spz[0];

        for (int t = 1; t < MM; t++) {
            ull ncx = pk2(-cx, -cx), ncy = pk2(-cy, -cy), ncz = pk2(-cz, -cz);
            float m[PPT];
#pragma unroll
            for (int p = 0; p < PAIRS; p++) {
                ull dx = add2(lx[p], ncx);                 // exact (p - c)
                ull dy = add2(ly[p], ncy);
                ull dz = add2(lz[p], ncz);
                ull s  = mul2(dx, dx);
                s = fma2(dy, dy, s);
                s = fma2(dz, dz, s);                       // reference-matched contraction
                float t0, t1; upk2(s, t0, t1);
                m[2 * p]     = fminf(md[2 * p],     t0); md[2 * p]     = m[2 * p];
                m[2 * p + 1] = fminf(md[2 * p + 1], t1); md[2 * p + 1] = m[2 * p + 1];
            }
            // tree max of 8 local mins
            float x0 = fmaxf(m[0], m[1]), x1 = fmaxf(m[2], m[3]);
            float x2 = fmaxf(m[4], m[5]), x3 = fmaxf(m[6], m[7]);
            float bvt = fmaxf(fmaxf(x0, x1), fmaxf(x2, x3));
            // warp max on bits (all >= 0 => bit-monotone)
            unsigned bvb = __float_as_uint(bvt);
            unsigned bw = redux_max_u32(bvb);
            if (lane == 0) swv[wid] = bw;
            __syncthreads();
            // block max: each lane loads one warp's max, redux across the warp
            unsigned bm = redux_max_u32(swv[lane]);
            if (bvb == bm) {
                int gi = -1;
#pragma unroll
                for (int j = PPT - 1; j >= 0; j--)          // descending => smallest j on ties
                    if (__float_as_uint(md[j]) == bm) gi = j * FPT + tid;
                if (gi >= 0) {
                    g_idx[b][t] = gi;
                    s_c[0] = spx[gi]; s_c[1] = spy[gi]; s_c[2] = spz[gi];
                }
            }
            __syncthreads();
            cx = s_c[0]; cy = s_c[1]; cz = s_c[2];
            if (tid == 0 && (t & 15) == 15) {
                __threadfence();
                atomicExch(&g_prog[b], t + 1);
            }
        }
        if (tid == 0) {
            __threadfence();
            atomicExch(&g_prog[b], MM);
        }
    } else if (blockIdx.x < BB + XBLOCKS) {
        // ===================== x_pre = x @ W_pre + b_pre (512 active) =====================
        if (tid >= XPT) return;
        float* sw = sp;                         // CIN*DMID floats
        float* sx = sp + CIN * DMID;            // XROWS * (CIN+4)
        const int bx = blockIdx.x - BB;
        const size_t row0 = (size_t)bx * XROWS;

        for (int i = tid; i < CIN * DMID; i += XPT) sw[i] = Wpre[i];
        for (int i = tid; i < XROWS * CIN; i += XPT)
            sx[(i >> 7) * (CIN + 4) + (i & 127)] = x[row0 * CIN + i];
        __syncthreads();

        const int r = tid >> 4, cq = tid & 15;
        float4 acc;
        acc.x = bpre[cq * 4 + 0]; acc.y = bpre[cq * 4 + 1];
        acc.z = bpre[cq * 4 + 2]; acc.w = bpre[cq * 4 + 3];
        const float4* sw4 = reinterpret_cast<const float4*>(sw);
#pragma unroll 8
        for (int k = 0; k < CIN; k++) {
            float  a = sx[r * (CIN + 4) + k];
            float4 w = sw4[k * 16 + cq];
            acc.x = fmaf(a, w.x, acc.x); acc.y = fmaf(a, w.y, acc.y);
            acc.z = fmaf(a, w.z, acc.z); acc.w = fmaf(a, w.w, acc.w);
        }
        float4* dst = reinterpret_cast<float4*>(&g_xpre[0][0][0]);
        dst[(row0 + r) * 16 + cq] = acc;
        __syncthreads();
        if (tid == 0) {
            __threadfence();
            atomicAdd(&g_xdone, 1);
        }
    } else {
        // ===================== conv: 8 centers, 256 active threads =====================
        if (tid >= 256) return;
        ConvSmem& sm = *reinterpret_cast<ConvSmem*>(sp);
        const int bx = blockIdx.x - (BB + XBLOCKS);
        const int b  = bx & 3;                       // interleave batches
        const int mg = (bx >> 2) * G8;               // ascending mg across bids
        const float* pb = pos + (size_t)b * NN * 3;

        // wait for producers (xpre fully done; FPS progressed past our centers)
        if (tid == 0) {
            while (*(volatile int*)&g_xdone < XBLOCKS) __nanosleep(256);
            const int need = mg + G8;
            while (*(volatile int*)&g_prog[b] < need) __nanosleep(256);
            __threadfence();
        }
        __syncthreads();

        if (tid < G8) {
            int pt = g_idx[b][mg + tid];
            sm.cpt[tid] = pt;
            sm.ccx[tid] = pb[3 * pt + 0];
            sm.ccy[tid] = pb[3 * pt + 1];
            sm.ccz[tid] = pb[3 * pt + 2];
            sm.cnt[tid] = 0;
        }
        if (tid < KK) {
            sm.kpx[tid] = kp[3 * tid + 0];
            sm.kpy[tid] = kp[3 * tid + 1];
            sm.kpz[tid] = kp[3 * tid + 2];
        }
        __syncthreads();

        for (int i = tid; i < G8 * CIN; i += 256) {
            int g = i >> 7, ci = i & 127;
            sm.xc[g][ci] = x[((size_t)b * NN + sm.cpt[g]) * CIN + ci];
        }

        ull cx2[G8 / 2], cy2[G8 / 2], cz2[G8 / 2];
#pragma unroll
        for (int gp = 0; gp < G8 / 2; gp++) {
            cx2[gp] = pk2(sm.ccx[2 * gp], sm.ccx[2 * gp + 1]);
            cy2[gp] = pk2(sm.ccy[2 * gp], sm.ccy[2 * gp + 1]);
            cz2[gp] = pk2(sm.ccz[2 * gp], sm.ccz[2 * gp + 1]);
        }

        for (int i = tid; i < NN; i += 256) {
            float px = pb[3 * i + 0], py = pb[3 * i + 1], pz = pb[3 * i + 2];
            ull npx = pk2(-px, -px), npy = pk2(-py, -py), npz = pk2(-pz, -pz);
#pragma unroll
            for (int gp = 0; gp < G8 / 2; gp++) {
                ull dx = add2(cx2[gp], npx);
                ull dy = add2(cy2[gp], npy);
                ull dz = add2(cz2[gp], npz);
                ull s  = mul2(dx, dx);
                s = fma2(dy, dy, s);
                s = fma2(dz, dz, s);
                float d0, d1; upk2(s, d0, d1);
                if (d0 <= R2C) {
                    int p = atomicAdd(&sm.cnt[2 * gp], 1);
                    if (p < CAP) { sm.nlist[2 * gp][p] = i; sm.nd2[2 * gp][p] = d0; }
                }
                if (d1 <= R2C) {
                    int p = atomicAdd(&sm.cnt[2 * gp + 1], 1);
                    if (p < CAP) { sm.nlist[2 * gp + 1][p] = i; sm.nd2[2 * gp + 1][p] = d1; }
                }
            }
        }
        __syncthreads();

        if (tid < G8) {
            int g = tid;
            int c = sm.cnt[g]; if (c > CAP) c = CAP;
            if (c > MAXNN) {
                for (int s = 0; s < MAXNN; s++) {
                    float bvd = 3.4e38f; int bpos = s; int bidx = 0x7fffffff;
                    for (int q = s; q < c; q++) {
                        float v = sm.nd2[g][q]; int ii = sm.nlist[g][q];
                        if (v < bvd || (v == bvd && ii < bidx)) { bvd = v; bpos = q; bidx = ii; }
                    }
                    float tv = sm.nd2[g][s]; int ti = sm.nlist[g][s];
                    sm.nd2[g][s] = bvd;  sm.nlist[g][s] = bidx;
                    sm.nd2[g][bpos] = tv; sm.nlist[g][bpos] = ti;
                }
                c = MAXNN;
            }
            sm.nsel[g] = c;
        }
        __syncthreads();

        for (int g = 0; g < G8; g++) {
            const int ne = sm.nsel[g];
            if (tid < MAXNN && tid < ne) {
                int p = sm.nlist[g][tid];
                sm.relx[tid] = pb[3 * p + 0] - sm.ccx[g];
                sm.rely[tid] = pb[3 * p + 1] - sm.ccy[g];
                sm.relz[tid] = pb[3 * p + 2] - sm.ccz[g];
            }
            for (int i = tid; i < ne * (DMID / 4); i += 256) {
                int e = i >> 4, dq = i & 15;
                const float4* src = reinterpret_cast<const float4*>(&g_xpre[b][sm.nlist[g][e]][0]);
                reinterpret_cast<float4*>(&sm.xjs[e][0])[dq] = src[dq];
            }
            __syncthreads();
            for (int i = tid; i < ne * KK; i += 256) {
                int e = i >> 4, k = i & 15;
                float dx = sm.relx[e] - sm.kpx[k];
                float dy = sm.rely[e] - sm.kpy[k];
                float dz = sm.relz[e] - sm.kpz[k];
                float dd = fmaf(dz, dz, fmaf(dy, dy, dx * dx)) + 1e-12f;
                float dist = sqrtf(dd);
                float v = 1.0f - dist / 0.1f;
                sm.infl[e][k] = v > 0.0f ? v : 0.0f;
            }
            __syncthreads();
            {
                int k = tid >> 4, dq = tid & 15;
                float4 a = make_float4(0.f, 0.f, 0.f, 0.f);
                const float4* xj4 = reinterpret_cast<const float4*>(&sm.xjs[0][0]);
                for (int e = 0; e < ne; e++) {
                    float  f  = sm.infl[e][k];
                    float4 xv = xj4[e * 16 + dq];
                    a.x = fmaf(f, xv.x, a.x); a.y = fmaf(f, xv.y, a.y);
                    a.z = fmaf(f, xv.z, a.z); a.w = fmaf(f, xv.w, a.w);
                }
                reinterpret_cast<float4*>(&sm.skd[g][k][0])[dq] = a;
            }
            __syncthreads();
        }

        // F[g][o] = sum_{kd} skd[g][kd] * kpW[kd][o]  (two acc[4] passes: reg-lean)
        {
            int o = tid & 63, p = tid >> 6;       // p in 0..3
            const float* skdf = &sm.skd[0][0][0];
#pragma unroll
            for (int h = 0; h < 2; h++) {
                float acc[4];
#pragma unroll
                for (int g = 0; g < 4; g++) acc[g] = 0.f;
                for (int kd = p * 256; kd < p * 256 + 256; kd++) {
                    float w = kpW[kd * DMID + o];
#pragma unroll
                    for (int g = 0; g < 4; g++)
                        acc[g] = fmaf(skdf[(h * 4 + g) * 1024 + kd], w, acc[g]);
                }
#pragma unroll
                for (int g = 0; g < 4; g++) sm.fpart[p][h * 4 + g][o] = acc[g];
            }
        }
        __syncthreads();
        for (int i = tid; i < G8 * DMID; i += 256) {
            int g = i >> 6, o = i & 63;
            sm.F[g][o] = sm.fpart[0][g][o] + sm.fpart[1][g][o] + sm.fpart[2][g][o] + sm.fpart[3][g][o];
        }
        __syncthreads();

        // out = F @ W_post + b_post + x_center @ W_sc + b_sc  (two acc[4] passes)
        {
            int c = tid;                 // 0..255
#pragma unroll
            for (int h = 0; h < 2; h++) {
                float acc[4];
                float bb0 = bpost[c] + bsc[c];
#pragma unroll
                for (int g = 0; g < 4; g++) acc[g] = bb0;
                for (int d = 0; d < DMID; d++) {
                    float w = Wpost[d * COUT + c];
#pragma unroll
                    for (int g = 0; g < 4; g++) acc[g] = fmaf(sm.F[h * 4 + g][d], w, acc[g]);
                }
                for (int ci = 0; ci < CIN; ci++) {
                    float w = Wsc[ci * COUT + c];
#pragma unroll
                    for (int g = 0; g < 4; g++) acc[g] = fmaf(sm.xc[h * 4 + g][ci], w, acc[g]);
                }
#pragma unroll
                for (int g = 0; g < 4; g++)
                    out_feat[((size_t)b * MM + mg + h * 4 + g) * COUT + c] = acc[g];
            }
        }
        if (tid < G8 * 3) {
            int g = tid / 3, cc = tid % 3;
            float v = (cc == 0) ? sm.ccx[g] : (cc == 1) ? sm.ccy[g] : sm.ccz[g];
            out_pos[((size_t)b * MM + mg + g) * 3 + cc] = v;
        }
    }
}

// ---------------- launch ----------------
extern "C" void kernel_launch(void* const* d_in, const int* in_sizes, int n_in,
                              void* d_out, int out_size) {
    const float* x     = (const float*)d_in[0];
    const float* pos   = (const float*)d_in[1];
    const float* Wpre  = (const float*)d_in[2];
    const float* bpre  = (const float*)d_in[3];
    const float* kp    = (const float*)d_in[4];
    const float* kpW   = (const float*)d_in[5];
    const float* Wpost = (const float*)d_in[6];
    const float* bpost = (const float*)d_in[7];
    const float* Wsc   = (const float*)d_in[8];
    const float* bsc   = (const float*)d_in[9];

    float* out_feat = (float*)d_out;
    float* out_pos  = out_feat + (size_t)BB * MM * COUT;

    cudaFuncSetAttribute(mega_kernel, cudaFuncAttributeMaxDynamicSharedMemorySize, 3 * NN * 4);

    init_kernel<<<1, 32>>>();
    int grid = BB + XBLOCKS + CONVBLOCKS;   // 4 + 1024 + 1024
    mega_kernel<<<grid, FPT, 3 * NN * 4>>>(
        pos, x, Wpre, bpre, kp, kpW, Wpost, bpost, Wsc, bsc, out_feat, out_pos);
}